// round 4
// baseline (speedup 1.0000x reference)
#include <cuda_runtime.h>
#include <stdint.h>

// TestSpatialTransform == two center crops of (4,2,192,192,192) -> (4,2,160,160,160).
// Pure HBM copy. Each thread: ONE crop position (d,h,w4), TWO bc-slices
// (bc, bc+4), BOTH tensors -> 4 independent LDG.128 front-batched, one index
// computation, ~36 regs so occupancy stays high (MLP x occupancy optimum).

#define PATCH 160
#define SRC   192
#define OFF   16
#define BC    8                        // B*C = 4*2
#define W4    (PATCH / 4)              // 40 float4 per row
#define SRC3  (SRC * SRC * SRC)        // floats per bc-slice
#define N_POS (PATCH * PATCH * W4)     // 1,024,000 positions (d,h,w4)
#define N_F4_PER_TENSOR (BC * N_POS)   // 8,192,000

__global__ void __launch_bounds__(256)
crop_copy4_kernel(const float* __restrict__ data,
                  const float* __restrict__ seg,
                  float4* __restrict__ out)
{
    int idx = blockIdx.x * blockDim.x + threadIdx.x;   // 0 .. 4*N_POS-1 exact

    int pos  = idx & (N_POS - 1) | 0;                  // N_POS not pow2; use div
    pos      = idx % N_POS;
    int bc0  = idx / N_POS;                            // 0..3
    int bc1  = bc0 + 4;

    int w4 = pos % W4;
    int t  = pos / W4;
    int h  = t % PATCH;
    int d  = t / PATCH;

    // source flat float index within one (192,192,192) slice
    int sidx = ((d + OFF) * SRC + (h + OFF)) * SRC + OFF + (w4 << 2);

    const float4* s_data0 = reinterpret_cast<const float4*>(data + sidx + bc0 * SRC3);
    const float4* s_data1 = reinterpret_cast<const float4*>(data + sidx + bc1 * SRC3);
    const float4* s_seg0  = reinterpret_cast<const float4*>(seg  + sidx + bc0 * SRC3);
    const float4* s_seg1  = reinterpret_cast<const float4*>(seg  + sidx + bc1 * SRC3);

    float4 a0 = __ldcs(s_data0);
    float4 a1 = __ldcs(s_data1);
    float4 b0 = __ldcs(s_seg0);
    float4 b1 = __ldcs(s_seg1);

    __stcs(out + pos + bc0 * N_POS, a0);
    __stcs(out + pos + bc1 * N_POS, a1);
    __stcs(out + pos + bc0 * N_POS + N_F4_PER_TENSOR, b0);
    __stcs(out + pos + bc1 * N_POS + N_F4_PER_TENSOR, b1);
}

extern "C" void kernel_launch(void* const* d_in, const int* in_sizes, int n_in,
                              void* d_out, int out_size)
{
    const float* data = (const float*)d_in[0];
    const float* seg  = (const float*)d_in[1];
    float4* out = (float4*)d_out;

    const int threads = 256;
    const int blocks  = (4 * N_POS) / threads;   // 16000 exactly, no tail
    crop_copy4_kernel<<<blocks, threads>>>(data, seg, out);
}

// round 5
// speedup vs baseline: 1.0192x; 1.0192x over previous
#include <cuda_runtime.h>
#include <stdint.h>

// TestSpatialTransform == two center crops of (4,2,192,192,192) -> (4,2,160,160,160).
// Pure HBM copy at minimum traffic (524 MB). Measured MLP sweep peaked at
// MLP=2 per thread (data+seg at same crop index): DRAM busy 83.7%, which is the
// mixed read/write stream ceiling on this part. This round: same shape,
// 512-thread blocks (fewer blocks, smoother tail), load/store interleaved.

#define PATCH 160
#define SRC   192
#define OFF   16
#define W4    (PATCH / 4)              // 40 float4 per row
#define N_F4_PER_TENSOR (8 * PATCH * PATCH * W4)   // 8,192,000

__global__ void __launch_bounds__(512)
crop_copy2b_kernel(const float* __restrict__ data,
                   const float* __restrict__ seg,
                   float4* __restrict__ out)
{
    int idx = blockIdx.x * blockDim.x + threadIdx.x;   // 0 .. N_F4_PER_TENSOR-1 exact

    int w4 = idx % W4;
    int t  = idx / W4;
    int h  = t % PATCH; t /= PATCH;
    int d  = t % PATCH;
    int bc = t / PATCH;

    // source flat float index within (8, 192, 192, 192)
    int sidx = (((bc * SRC) + (d + OFF)) * SRC + (h + OFF)) * SRC + OFF + (w4 << 2);

    float4 a = __ldcs(reinterpret_cast<const float4*>(data + sidx));
    float4 b = __ldcs(reinterpret_cast<const float4*>(seg  + sidx));

    __stcs(out + idx, a);
    __stcs(out + idx + N_F4_PER_TENSOR, b);
}

extern "C" void kernel_launch(void* const* d_in, const int* in_sizes, int n_in,
                              void* d_out, int out_size)
{
    const float* data = (const float*)d_in[0];
    const float* seg  = (const float*)d_in[1];
    float4* out = (float4*)d_out;

    const int threads = 512;
    const int blocks  = N_F4_PER_TENSOR / threads;   // 16000 exactly, no tail
    crop_copy2b_kernel<<<blocks, threads>>>(data, seg, out);
}